// round 7
// baseline (speedup 1.0000x reference)
#include <cuda_runtime.h>

#define N_NODES 50000
#define N_EDGES 800000
#define D 64
#define OCC 6
#define GRID (148 * OCC)                 // 888 blocks; <= 912 co-resident on 152-SM GB300
#define TPB 256
#define NT ((N_NODES + 31) / 32)         // 1563 tiles of 32 rows
#define CH ((N_NODES + GRID - 1) / GRID) // 57 nodes per block chunk
#define DCHUNK ((GRID + TPB - 1) / TPB)  // 4: chunk-sums per thread in phase D

// ---------------- scratch (static device globals; no allocation) ----------------
__device__ int   g_degcnt[N_NODES];
__device__ int   g_cursor[N_NODES];
__device__ int   g_rs[N_NODES + 1];      // CSR row starts
__device__ int   g_csr[N_EDGES];         // CSR column (src) indices
__device__ int   g_bsum[GRID];
__device__ int   g_boff[GRID];
__device__ int   g_tile[2];              // dynamic tile counters (one per layer)
__device__ float g_h[N_NODES * D];

// barrier state: monotonic, never reset (safe across graph replays)
__device__ unsigned g_bcnt = 0;
__device__ unsigned g_bgen = 0;

__device__ __forceinline__ void grid_bar() {
    __syncthreads();
    if (threadIdx.x == 0) {
        __threadfence();
        unsigned my = atomicAdd(&g_bcnt, 1u) + 1u;
        unsigned need = (my + GRID - 1u) / GRID;
        if ((my % GRID) == 0u) atomicAdd(&g_bgen, 1u);
        while (*((volatile unsigned*)&g_bgen) < need) {}
        __threadfence();
    }
    __syncthreads();
}

__device__ __forceinline__ int load_idx(const void* p, int e, bool is64) {
    return is64 ? (int)((const long long*)p)[e] : ((const int*)p)[e];
}

// ---------------- fused persistent kernel ----------------
__global__ void __launch_bounds__(TPB, OCC)
sage_fused_kernel(const float* __restrict__ x,
                  const void* __restrict__ srcp,
                  const void* __restrict__ dstp,
                  const float* __restrict__ W_self0, const float* __restrict__ W_neigh0,
                  const float* __restrict__ b0,
                  const float* __restrict__ W_self1, const float* __restrict__ W_neigh1,
                  const float* __restrict__ b1,
                  float* __restrict__ outp) {
    const int tid = threadIdx.x;
    const int bid = blockIdx.x;
    const int gtid = bid * TPB + tid;
    const int gstride = GRID * TPB;

    __shared__ float At[32][65];      // 8.3 KB padded input tile
    __shared__ int   sscan[TPB];      // 1 KB scan scratch
    __shared__ int   rb[33];          // tile row bounds
    __shared__ int   s_t;             // dynamic tile id

    // ---- index dtype detection (every block computes identically) ----
    if (tid == 0) sscan[0] = 0;
    __syncthreads();
    {
        int any = 0;
        const int* si = (const int*)srcp;
        for (int i = tid; i < 2048; i += TPB) any |= si[2 * i + 1];
        if (any) atomicOr(&sscan[0], 1);
    }
    __syncthreads();
    const bool is64 = (sscan[0] == 0);   // high words all zero -> int64 little-endian

    // ---- phase A: zero counters ----
    for (int j = gtid; j < N_NODES; j += gstride) { g_degcnt[j] = 0; g_cursor[j] = 0; }
    if (gtid < 2) g_tile[gtid] = 0;
    grid_bar();

    // ---- phase B: degree histogram ----
    for (int e = gtid; e < N_EDGES; e += gstride)
        atomicAdd(&g_degcnt[load_idx(dstp, e, is64)], 1);
    grid_bar();

    // ---- phase C: per-block chunk sums ----
    {
        int n0 = bid * CH;
        int n = N_NODES - n0; if (n > CH) n = CH; if (n < 0) n = 0;
        int v = (tid < n) ? g_degcnt[n0 + tid] : 0;
        sscan[tid] = v; __syncthreads();
        for (int off = TPB / 2; off > 0; off >>= 1) {
            if (tid < off) sscan[tid] += sscan[tid + off];
            __syncthreads();
        }
        if (tid == 0) g_bsum[bid] = sscan[0];
    }
    grid_bar();

    // ---- phase D: block 0 scans the GRID chunk sums ----
    if (bid == 0) {
        int v[DCHUNK]; int mysum = 0;
#pragma unroll
        for (int k = 0; k < DCHUNK; k++) {
            int idx = tid * DCHUNK + k;
            v[k] = (idx < GRID) ? g_bsum[idx] : 0;
            mysum += v[k];
        }
        sscan[tid] = mysum; __syncthreads();
        for (int off = 1; off < TPB; off <<= 1) {
            int t = (tid >= off) ? sscan[tid - off] : 0;
            __syncthreads();
            sscan[tid] += t;
            __syncthreads();
        }
        int run = sscan[tid] - mysum;   // exclusive prefix of thread sums
#pragma unroll
        for (int k = 0; k < DCHUNK; k++) {
            int idx = tid * DCHUNK + k;
            if (idx < GRID) g_boff[idx] = run;
            run += v[k];
        }
    }
    grid_bar();

    // ---- phase E: per-chunk exclusive scan -> row starts ----
    {
        int n0 = bid * CH;
        int n = N_NODES - n0; if (n > CH) n = CH; if (n < 0) n = 0;
        int v = (tid < n) ? g_degcnt[n0 + tid] : 0;
        sscan[tid] = v; __syncthreads();
        for (int off = 1; off < TPB; off <<= 1) {
            int t = (tid >= off) ? sscan[tid - off] : 0;
            __syncthreads();
            sscan[tid] += t;
            __syncthreads();
        }
        if (tid < n) g_rs[n0 + tid] = g_boff[bid] + sscan[tid] - v;
        if (bid == 0 && tid == 0) g_rs[N_NODES] = N_EDGES;
    }
    grid_bar();

    // ---- phase F: fill CSR ----
    for (int e = gtid; e < N_EDGES; e += gstride) {
        int dn = load_idx(dstp, e, is64);
        int s  = load_idx(srcp, e, is64);
        int pos = atomicAdd(&g_cursor[dn], 1);
        g_csr[g_rs[dn] + pos] = s;
    }
    grid_bar();

    // ---- fused layer: out = [relu](in@Wself + mean_gather(in)@Wneigh + b) ----
    const int tc = tid & 15;     // col group: cols 4*tc..4*tc+3 (lane-in-halfwarp)
    const int tr = tid >> 4;     // 0..15: halfwarp id, owns rows tr*2, tr*2+1

#define SAGE_LAYER(IN, WSELF, WNEIGH, BIAS, OUT, RELU, LYR)                               \
    {                                                                                     \
        const float* inp = (IN);                                                          \
        for (;;) {                                                                        \
            __syncthreads();                                                              \
            if (tid == 0) s_t = atomicAdd(&g_tile[LYR], 1);                               \
            __syncthreads();                                                              \
            const int t = s_t;                                                            \
            if (t >= NT) break;                                                           \
            const int row0 = t * 32;                                                      \
            if (tid < 33) {                                                               \
                int rr = row0 + tid; if (rr > N_NODES) rr = N_NODES;                      \
                rb[tid] = g_rs[rr];                                                       \
            }                                                                             \
            /* self features into At */                                                   \
            _Pragma("unroll") for (int j = 0; j < 2; j++) {                               \
                int idx = tid + j * TPB;                                                  \
                int r = idx >> 4, c = idx & 15;                                           \
                int gr = row0 + r;                                                        \
                float4 v = make_float4(0.f, 0.f, 0.f, 0.f);                               \
                if (gr < N_NODES) v = ((const float4*)(inp + (long long)gr * D))[c];      \
                At[r][c*4] = v.x; At[r][c*4+1] = v.y;                                     \
                At[r][c*4+2] = v.z; At[r][c*4+3] = v.w;                                   \
            }                                                                             \
            __syncthreads();                                                              \
            float acc[2][4];                                                              \
            _Pragma("unroll") for (int i = 0; i < 2; i++)                                 \
                _Pragma("unroll") for (int j = 0; j < 4; j++) acc[i][j] = 0.f;            \
            _Pragma("unroll 4") for (int k = 0; k < D; k++) {                             \
                float4 w = __ldg((const float4*)((WSELF) + k * D) + tc);                  \
                float p0 = At[tr*2][k], p1 = At[tr*2+1][k];                               \
                acc[0][0] += p0*w.x; acc[0][1] += p0*w.y;                                 \
                acc[0][2] += p0*w.z; acc[0][3] += p0*w.w;                                 \
                acc[1][0] += p1*w.x; acc[1][1] += p1*w.y;                                 \
                acc[1][2] += p1*w.z; acc[1][3] += p1*w.w;                                 \
            }                                                                             \
            __syncthreads();                                                              \
            /* gather mean of neighbors into At (halfwarp tr owns 2 rows) */              \
            _Pragma("unroll") for (int i = 0; i < 2; i++) {                               \
                int r = tr * 2 + i;                                                       \
                int gr = row0 + r;                                                        \
                float4 a0 = make_float4(0,0,0,0), a1 = a0;                                \
                float iv = 0.f;                                                           \
                if (gr < N_NODES) {                                                       \
                    int e = rb[r], lend = rb[r + 1];                                      \
                    iv = 1.0f / fmaxf((float)(lend - e), 1.0f);                           \
                    for (; e + 1 < lend; e += 2) {                                        \
                        int s0 = g_csr[e], s1 = g_csr[e + 1];                             \
                        float4 v0 = __ldg((const float4*)(inp + (long long)s0 * D) + tc); \
                        float4 v1 = __ldg((const float4*)(inp + (long long)s1 * D) + tc); \
                        a0.x+=v0.x; a0.y+=v0.y; a0.z+=v0.z; a0.w+=v0.w;                   \
                        a1.x+=v1.x; a1.y+=v1.y; a1.z+=v1.z; a1.w+=v1.w;                   \
                    }                                                                     \
                    if (e < lend) {                                                       \
                        int s0 = g_csr[e];                                                \
                        float4 v0 = __ldg((const float4*)(inp + (long long)s0 * D) + tc); \
                        a0.x+=v0.x; a0.y+=v0.y; a0.z+=v0.z; a0.w+=v0.w;                   \
                    }                                                                     \
                }                                                                         \
                At[r][tc*4]   = (a0.x + a1.x) * iv;                                       \
                At[r][tc*4+1] = (a0.y + a1.y) * iv;                                       \
                At[r][tc*4+2] = (a0.z + a1.z) * iv;                                       \
                At[r][tc*4+3] = (a0.w + a1.w) * iv;                                       \
            }                                                                             \
            __syncthreads();                                                              \
            _Pragma("unroll 4") for (int k = 0; k < D; k++) {                             \
                float4 w = __ldg((const float4*)((WNEIGH) + k * D) + tc);                 \
                float p0 = At[tr*2][k], p1 = At[tr*2+1][k];                               \
                acc[0][0] += p0*w.x; acc[0][1] += p0*w.y;                                 \
                acc[0][2] += p0*w.z; acc[0][3] += p0*w.w;                                 \
                acc[1][0] += p1*w.x; acc[1][1] += p1*w.y;                                 \
                acc[1][2] += p1*w.z; acc[1][3] += p1*w.w;                                 \
            }                                                                             \
            float4 bv = __ldg((const float4*)(BIAS) + tc);                                \
            _Pragma("unroll") for (int i = 0; i < 2; i++) {                               \
                int gr = row0 + tr * 2 + i;                                               \
                if (gr < N_NODES) {                                                       \
                    float4 o;                                                             \
                    o.x = acc[i][0] + bv.x; o.y = acc[i][1] + bv.y;                       \
                    o.z = acc[i][2] + bv.z; o.w = acc[i][3] + bv.w;                       \
                    if (RELU) { o.x=fmaxf(o.x,0.f); o.y=fmaxf(o.y,0.f);                   \
                                o.z=fmaxf(o.z,0.f); o.w=fmaxf(o.w,0.f); }                 \
                    ((float4*)((OUT) + (long long)gr * D))[tc] = o;                       \
                }                                                                         \
            }                                                                             \
        }                                                                                 \
    }

    // ---- phase G: layer 0 -> g_h (relu) ----
    SAGE_LAYER(x, W_self0, W_neigh0, b0, g_h, true, 0)
    grid_bar();

    // ---- phase H: layer 1 -> out (no relu) ----
    SAGE_LAYER(g_h, W_self1, W_neigh1, b1, outp, false, 1)
}

// ---------------- launch: ONE kernel = ONE graph node ----------------
extern "C" void kernel_launch(void* const* d_in, const int* in_sizes, int n_in,
                              void* d_out, int out_size) {
    const float* x        = (const float*)d_in[0];
    const void*  src      = d_in[1];
    const void*  dst      = d_in[2];
    const float* W_self0  = (const float*)d_in[3];
    const float* W_neigh0 = (const float*)d_in[4];
    const float* b0       = (const float*)d_in[5];
    const float* W_self1  = (const float*)d_in[6];
    const float* W_neigh1 = (const float*)d_in[7];
    const float* b1       = (const float*)d_in[8];
    float* outp = (float*)d_out;

    sage_fused_kernel<<<GRID, TPB>>>(x, src, dst,
                                     W_self0, W_neigh0, b0,
                                     W_self1, W_neigh1, b1, outp);
}

// round 8
// speedup vs baseline: 1.2152x; 1.2152x over previous
#include <cuda_runtime.h>

#define N_NODES 50000
#define N_EDGES 800000
#define D 64
#define GRID 592                         // 148 SMs x 4 blocks/SM (one wave incl. 152-SM GB300)
#define TPB 256
#define NT ((N_NODES + 31) / 32)         // 1563 tiles of 32 rows
#define CH ((N_NODES + GRID - 1) / GRID) // 85 nodes per block chunk
#define SIDX_CAP 1024                    // smem CSR stage capacity (avg tile = 512 edges)

typedef unsigned long long ull;

// ---------------- scratch (static device globals; no allocation) ----------------
__device__ int   g_degcnt[N_NODES];
__device__ int   g_cursor[N_NODES];
__device__ int   g_rs[N_NODES + 1];      // CSR row starts
__device__ int   g_csr[N_EDGES];         // CSR column (src) indices
__device__ int   g_bsum[GRID];
__device__ int   g_boff[GRID];
__device__ int   g_tile[2];              // dynamic tile counters (one per layer)
__device__ float g_h[N_NODES * D];

// barrier state: monotonic, never reset (safe across graph replays)
__device__ unsigned g_bcnt = 0;
__device__ unsigned g_bgen = 0;

__device__ __forceinline__ void grid_bar() {
    __syncthreads();
    if (threadIdx.x == 0) {
        __threadfence();
        unsigned my = atomicAdd(&g_bcnt, 1u) + 1u;
        unsigned need = (my + GRID - 1u) / GRID;
        if ((my % GRID) == 0u) atomicAdd(&g_bgen, 1u);
        while (*((volatile unsigned*)&g_bgen) < need) {}
        __threadfence();
    }
    __syncthreads();
}

__device__ __forceinline__ int load_idx(const void* p, int e, bool is64) {
    return is64 ? (int)((const long long*)p)[e] : ((const int*)p)[e];
}

// ---------------- f32x2 packed helpers (Blackwell FFMA2 path) ----------------
__device__ __forceinline__ ull pack2(float a) {
    ull r;
    asm("mov.b64 %0, {%1, %1};" : "=l"(r) : "r"(__float_as_uint(a)));
    return r;
}
__device__ __forceinline__ void ffma2(ull& d, ull a, ull b) {
    asm("fma.rn.f32x2 %0, %1, %2, %0;" : "+l"(d) : "l"(a), "l"(b));
}
__device__ __forceinline__ void fadd2(ull& d, ull v) {
    asm("add.rn.f32x2 %0, %0, %1;" : "+l"(d) : "l"(v));
}
__device__ __forceinline__ ull fadd2r(ull a, ull b) {
    ull r;
    asm("add.rn.f32x2 %0, %1, %2;" : "=l"(r) : "l"(a), "l"(b));
    return r;
}
__device__ __forceinline__ ull fmul2(ull a, ull b) {
    ull r;
    asm("mul.rn.f32x2 %0, %1, %2;" : "=l"(r) : "l"(a), "l"(b));
    return r;
}
__device__ __forceinline__ float lo2(ull v) { return __uint_as_float((unsigned)(v)); }
__device__ __forceinline__ float hi2(ull v) { return __uint_as_float((unsigned)(v >> 32)); }

// ---------------- fused persistent kernel ----------------
__global__ void __launch_bounds__(TPB, 4)
sage_fused_kernel(const float* __restrict__ x,
                  const void* __restrict__ srcp,
                  const void* __restrict__ dstp,
                  const float* __restrict__ W_self0, const float* __restrict__ W_neigh0,
                  const float* __restrict__ b0,
                  const float* __restrict__ W_self1, const float* __restrict__ W_neigh1,
                  const float* __restrict__ b1,
                  float* __restrict__ outp) {
    const int tid = threadIdx.x;
    const int bid = blockIdx.x;
    const int gtid = bid * TPB + tid;
    const int gstride = GRID * TPB;

    __shared__ __align__(16) float Wsm[2][D * D];   // 32 KB both weights of current layer
    __shared__ __align__(16) float At[32][66];      // 8.45 KB padded tile (66 even -> 8B rows)
    __shared__ int   sidx[SIDX_CAP];  // 4 KB staged CSR indices (aliased as scan scratch)
    __shared__ int   rb[33];          // tile row bounds
    __shared__ int   s_t;             // dynamic tile id
    int* sscan = sidx;                // alias: scan scratch only used in CSR-build phases

    // ---- index dtype detection (every block computes identically) ----
    if (tid == 0) sscan[0] = 0;
    __syncthreads();
    {
        int any = 0;
        const int* si = (const int*)srcp;
        for (int i = tid; i < 2048; i += TPB) any |= si[2 * i + 1];
        if (any) atomicOr(&sscan[0], 1);
    }
    __syncthreads();
    const bool is64 = (sscan[0] == 0);   // high words all zero -> int64 little-endian

    // ---- phase A: zero counters ----
    for (int j = gtid; j < N_NODES; j += gstride) { g_degcnt[j] = 0; g_cursor[j] = 0; }
    if (gtid < 2) g_tile[gtid] = 0;
    grid_bar();

    // ---- phase B: degree histogram ----
    for (int e = gtid; e < N_EDGES; e += gstride)
        atomicAdd(&g_degcnt[load_idx(dstp, e, is64)], 1);
    grid_bar();

    // ---- phase C: per-block chunk sums ----
    {
        int n0 = bid * CH;
        int n = N_NODES - n0; if (n > CH) n = CH; if (n < 0) n = 0;
        int v = (tid < n) ? g_degcnt[n0 + tid] : 0;
        sscan[tid] = v; __syncthreads();
        for (int off = TPB / 2; off > 0; off >>= 1) {
            if (tid < off) sscan[tid] += sscan[tid + off];
            __syncthreads();
        }
        if (tid == 0) g_bsum[bid] = sscan[0];
    }
    grid_bar();

    // ---- phase D: block 0 scans the 592 chunk sums ----
    if (bid == 0) {
        int v[3]; int mysum = 0;
#pragma unroll
        for (int k = 0; k < 3; k++) {
            int idx = tid * 3 + k;
            v[k] = (idx < GRID) ? g_bsum[idx] : 0;
            mysum += v[k];
        }
        sscan[tid] = mysum; __syncthreads();
        for (int off = 1; off < TPB; off <<= 1) {
            int t = (tid >= off) ? sscan[tid - off] : 0;
            __syncthreads();
            sscan[tid] += t;
            __syncthreads();
        }
        int run = sscan[tid] - mysum;   // exclusive prefix of thread sums
#pragma unroll
        for (int k = 0; k < 3; k++) {
            int idx = tid * 3 + k;
            if (idx < GRID) g_boff[idx] = run;
            run += v[k];
        }
    }
    grid_bar();

    // ---- phase E: per-chunk exclusive scan -> row starts ----
    {
        int n0 = bid * CH;
        int n = N_NODES - n0; if (n > CH) n = CH; if (n < 0) n = 0;
        int v = (tid < n) ? g_degcnt[n0 + tid] : 0;
        sscan[tid] = v; __syncthreads();
        for (int off = 1; off < TPB; off <<= 1) {
            int t = (tid >= off) ? sscan[tid - off] : 0;
            __syncthreads();
            sscan[tid] += t;
            __syncthreads();
        }
        if (tid < n) g_rs[n0 + tid] = g_boff[bid] + sscan[tid] - v;
        if (bid == 0 && tid == 0) g_rs[N_NODES] = N_EDGES;
    }
    grid_bar();

    // ---- phase F: fill CSR ----
    for (int e = gtid; e < N_EDGES; e += gstride) {
        int dn = load_idx(dstp, e, is64);
        int s  = load_idx(srcp, e, is64);
        int pos = atomicAdd(&g_cursor[dn], 1);
        g_csr[g_rs[dn] + pos] = s;
    }
    grid_bar();

    // ---- fused layer: out = [relu](in@Wself + mean_gather(in)@Wneigh + b) ----
    const int tc = tid & 15;     // col group: cols 4*tc..4*tc+3 (lane-in-halfwarp)
    const int tr = tid >> 4;     // 0..15: halfwarp id, owns rows tr*2, tr*2+1

#define GATHER_ACCUM(IDX_EXPR)                                                            \
    {                                                                                     \
        int e = lbeg;                                                                     \
        for (; e + 3 < lend; e += 4) {                                                    \
            int s0 = (IDX_EXPR(e));     int s1 = (IDX_EXPR(e + 1));                       \
            int s2 = (IDX_EXPR(e + 2)); int s3 = (IDX_EXPR(e + 3));                       \
            ulonglong2 v0 = *(const ulonglong2*)(inp + (long long)s0 * D + tc * 4);       \
            ulonglong2 v1 = *(const ulonglong2*)(inp + (long long)s1 * D + tc * 4);       \
            ulonglong2 v2 = *(const ulonglong2*)(inp + (long long)s2 * D + tc * 4);       \
            ulonglong2 v3 = *(const ulonglong2*)(inp + (long long)s3 * D + tc * 4);       \
            fadd2(a0l, v0.x); fadd2(a0h, v0.y);                                           \
            fadd2(a1l, v1.x); fadd2(a1h, v1.y);                                           \
            fadd2(a2l, v2.x); fadd2(a2h, v2.y);                                           \
            fadd2(a3l, v3.x); fadd2(a3h, v3.y);                                           \
        }                                                                                 \
        for (; e < lend; e++) {                                                           \
            int s0 = (IDX_EXPR(e));                                                       \
            ulonglong2 v0 = *(const ulonglong2*)(inp + (long long)s0 * D + tc * 4);       \
            fadd2(a0l, v0.x); fadd2(a0h, v0.y);                                           \
        }                                                                                 \
    }
#define IDX_SMEM(E)  sidx[E]
#define IDX_GMEM(E)  g_csr[ebase + (E)]

#define GEMM_PASS(WIDX)                                                                   \
    {                                                                                     \
        const float* A0 = At[tr * 2];                                                     \
        const float* A1 = At[tr * 2 + 1];                                                 \
        const float* W  = Wsm[WIDX];                                                      \
        _Pragma("unroll 8") for (int k = 0; k < D; k += 2) {                              \
            float2 p0 = *(const float2*)&A0[k];                                           \
            float2 p1 = *(const float2*)&A1[k];                                           \
            ulonglong2 w0 = *(const ulonglong2*)&W[k * D + tc * 4];                       \
            ulonglong2 w1 = *(const ulonglong2*)&W[(k + 1) * D + tc * 4];                 \
            ull pa;                                                                       \
            pa = pack2(p0.x); ffma2(acc00, pa, w0.x); ffma2(acc01, pa, w0.y);             \
            pa = pack2(p1.x); ffma2(acc10, pa, w0.x); ffma2(acc11, pa, w0.y);             \
            pa = pack2(p0.y); ffma2(acc00, pa, w1.x); ffma2(acc01, pa, w1.y);             \
            pa = pack2(p1.y); ffma2(acc10, pa, w1.x); ffma2(acc11, pa, w1.y);             \
        }                                                                                 \
    }

#define SAGE_LAYER(IN, WSELF, WNEIGH, BIAS, OUT, RELU, LYR)                               \
    {                                                                                     \
        const float* inp = (IN);                                                          \
        _Pragma("unroll") for (int j = 0; j < 4; j++) {                                   \
            int idx = tid + j * TPB;                                                      \
            ((float4*)Wsm[0])[idx] = ((const float4*)(WSELF))[idx];                       \
            ((float4*)Wsm[1])[idx] = ((const float4*)(WNEIGH))[idx];                      \
        }                                                                                 \
        for (;;) {                                                                        \
            __syncthreads();                                                              \
            if (tid == 0) s_t = atomicAdd(&g_tile[LYR], 1);                               \
            __syncthreads();                                                              \
            const int t = s_t;                                                            \
            if (t >= NT) break;                                                           \
            const int row0 = t * 32;                                                      \
            if (tid < 33) {                                                               \
                int rr = row0 + tid; if (rr > N_NODES) rr = N_NODES;                      \
                rb[tid] = g_rs[rr];                                                       \
            }                                                                             \
            __syncthreads();                                                              \
            const int ebase = rb[0];                                                      \
            const int ecnt  = rb[32] - ebase;                                             \
            const bool fits = (ecnt <= SIDX_CAP);                                         \
            if (fits) for (int j = tid; j < ecnt; j += TPB) sidx[j] = g_csr[ebase + j];   \
            /* self features into At */                                                   \
            _Pragma("unroll") for (int j = 0; j < 2; j++) {                               \
                int idx = tid + j * TPB;                                                  \
                int r = idx >> 4, c = idx & 15;                                           \
                int gr = row0 + r;                                                        \
                float4 v = make_float4(0.f, 0.f, 0.f, 0.f);                               \
                if (gr < N_NODES) v = ((const float4*)(inp + (long long)gr * D))[c];      \
                At[r][c*4] = v.x; At[r][c*4+1] = v.y;                                     \
                At[r][c*4+2] = v.z; At[r][c*4+3] = v.w;                                   \
            }                                                                             \
            __syncthreads();                                                              \
            ull acc00 = 0, acc01 = 0, acc10 = 0, acc11 = 0;                               \
            GEMM_PASS(0)                                                                  \
            __syncthreads();                                                              \
            /* gather mean of neighbors into At (halfwarp tr owns 2 rows) */              \
            _Pragma("unroll") for (int i = 0; i < 2; i++) {                               \
                int r = tr * 2 + i;                                                       \
                int gr = row0 + r;                                                        \
                ull a0l = 0, a0h = 0, a1l = 0, a1h = 0;                                   \
                ull a2l = 0, a2h = 0, a3l = 0, a3h = 0;                                   \
                float iv = 0.f;                                                           \
                if (gr < N_NODES) {                                                       \
                    int lbeg = rb[r] - ebase, lend = rb[r + 1] - ebase;                   \
                    if (fits) GATHER_ACCUM(IDX_SMEM)                                      \
                    else      GATHER_ACCUM(IDX_GMEM)                                      \
                    iv = 1.0f / fmaxf((float)(lend - lbeg), 1.0f);                        \
                }                                                                         \
                ull piv = pack2(iv);                                                      \
                ull slo = fmul2(fadd2r(fadd2r(a0l, a1l), fadd2r(a2l, a3l)), piv);         \
                ull shi = fmul2(fadd2r(fadd2r(a0h, a1h), fadd2r(a2h, a3h)), piv);         \
                *(ull*)&At[r][tc * 4]     = slo;                                          \
                *(ull*)&At[r][tc * 4 + 2] = shi;                                          \
            }                                                                             \
            __syncthreads();                                                              \
            GEMM_PASS(1)                                                                  \
            float4 bv = ((const float4*)(BIAS))[tc];                                      \
            _Pragma("unroll") for (int i = 0; i < 2; i++) {                               \
                int gr = row0 + tr * 2 + i;                                               \
                if (gr < N_NODES) {                                                       \
                    ull alo = i ? acc10 : acc00;                                          \
                    ull ahi = i ? acc11 : acc01;                                          \
                    float4 o;                                                             \
                    o.x = lo2(alo) + bv.x; o.y = hi2(alo) + bv.y;                         \
                    o.z = lo2(ahi) + bv.z; o.w = hi2(ahi) + bv.w;                         \
                    if (RELU) { o.x=fmaxf(o.x,0.f); o.y=fmaxf(o.y,0.f);                   \
                                o.z=fmaxf(o.z,0.f); o.w=fmaxf(o.w,0.f); }                 \
                    ((float4*)((OUT) + (long long)gr * D))[tc] = o;                       \
                }                                                                         \
            }                                                                             \
        }                                                                                 \
    }

    // ---- phase G: layer 0 -> g_h (relu) ----
    SAGE_LAYER(x, W_self0, W_neigh0, b0, g_h, true, 0)
    grid_bar();

    // ---- phase H: layer 1 -> out (no relu) ----
    SAGE_LAYER(g_h, W_self1, W_neigh1, b1, outp, false, 1)
}

// ---------------- launch: ONE kernel = ONE graph node ----------------
extern "C" void kernel_launch(void* const* d_in, const int* in_sizes, int n_in,
                              void* d_out, int out_size) {
    const float* x        = (const float*)d_in[0];
    const void*  src      = d_in[1];
    const void*  dst      = d_in[2];
    const float* W_self0  = (const float*)d_in[3];
    const float* W_neigh0 = (const float*)d_in[4];
    const float* b0       = (const float*)d_in[5];
    const float* W_self1  = (const float*)d_in[6];
    const float* W_neigh1 = (const float*)d_in[7];
    const float* b1       = (const float*)d_in[8];
    float* outp = (float*)d_out;

    sage_fused_kernel<<<GRID, TPB>>>(x, src, dst,
                                     W_self0, W_neigh0, b0,
                                     W_self1, W_neigh1, b1, outp);
}